// round 1
// baseline (speedup 1.0000x reference)
#include <cuda_runtime.h>
#include <math.h>

#define B_  2
#define S_  2048
#define D_  512
#define H_  8
#define HD_ 64
#define NBH 16   // B_*H_

// Scratch (static __device__ — no allocations allowed)
__device__ float g_q[(size_t)NBH * S_ * HD_];
__device__ float g_k[(size_t)NBH * S_ * HD_];
__device__ float g_v[(size_t)NBH * S_ * HD_];
__device__ float g_fi[(size_t)NBH * S_];
__device__ float g_ctx[(size_t)B_ * S_ * D_];

// ---------------------------------------------------------------------------
// Generic 128x128x8 fp32 tiled GEMM, 256 threads, 8x8 micro-tile.
// mode 0: C = A@B + bias (row-major)         [unused]
// mode 1: qkv scatter epilogue -> g_q/g_k/g_v head layout
// mode 2: A := g_ctx internally, C = A@B + bias (proj)
// ---------------------------------------------------------------------------
__global__ __launch_bounds__(256)
void sgemm128(const float* __restrict__ A, const float* __restrict__ Bm,
              const float* __restrict__ bias, float* __restrict__ C,
              int M, int N, int K, int mode)
{
    if (mode == 2) A = g_ctx;
    __shared__ float As[8][128];   // transposed A tile: As[k][m]
    __shared__ float Bs[8][128];

    const int tid = threadIdx.x;
    const int tx = tid & 15, ty = tid >> 4;
    const int m0 = blockIdx.y << 7, n0 = blockIdx.x << 7;

    const int arow = tid >> 1, acol = (tid & 1) << 2;
    const int brow = tid >> 5, bcol = (tid & 31) << 2;

    const float* Ap = A  + (size_t)(m0 + arow) * K + acol;
    const float* Bp = Bm + (size_t)brow * N + n0 + bcol;

    float acc[8][8];
#pragma unroll
    for (int i = 0; i < 8; ++i)
#pragma unroll
        for (int j = 0; j < 8; ++j) acc[i][j] = 0.f;

    for (int k0 = 0; k0 < K; k0 += 8) {
        float4 av = *(const float4*)(Ap + k0);
        float4 bv = *(const float4*)(Bp + (size_t)k0 * N);
        As[acol + 0][arow] = av.x;
        As[acol + 1][arow] = av.y;
        As[acol + 2][arow] = av.z;
        As[acol + 3][arow] = av.w;
        *(float4*)&Bs[brow][bcol] = bv;
        __syncthreads();
#pragma unroll
        for (int kk = 0; kk < 8; ++kk) {
            float4 a0 = *(const float4*)&As[kk][ty << 3];
            float4 a1 = *(const float4*)&As[kk][(ty << 3) + 4];
            float4 b0 = *(const float4*)&Bs[kk][tx << 3];
            float4 b1 = *(const float4*)&Bs[kk][(tx << 3) + 4];
            float am[8] = {a0.x,a0.y,a0.z,a0.w,a1.x,a1.y,a1.z,a1.w};
            float bn[8] = {b0.x,b0.y,b0.z,b0.w,b1.x,b1.y,b1.z,b1.w};
#pragma unroll
            for (int i = 0; i < 8; ++i)
#pragma unroll
                for (int j = 0; j < 8; ++j)
                    acc[i][j] += am[i] * bn[j];
        }
        __syncthreads();
    }

    if (mode != 1) {
#pragma unroll
        for (int i = 0; i < 8; ++i) {
            int m = m0 + (ty << 3) + i;
            float* cp = C + (size_t)m * N + n0 + (tx << 3);
            const float* bp2 = bias + n0 + (tx << 3);
#pragma unroll
            for (int j = 0; j < 8; ++j) cp[j] = acc[i][j] + bp2[j];
        }
    } else {
        // qkv scatter: n -> (which of q/k/v, head, hd). 8 consecutive n stay
        // within one head chunk (all boundaries are multiples of 8).
        int n_base = n0 + (tx << 3);
        int t  = n_base >> 9;       // 0:q 1:k 2:v
        int cc = n_base & 511;
        int h  = cc >> 6, hd = cc & 63;
        float* dst = (t == 0) ? g_q : (t == 1) ? g_k : g_v;
        const float* bp2 = bias + n_base;
#pragma unroll
        for (int i = 0; i < 8; ++i) {
            int m = m0 + (ty << 3) + i;
            int b = m >> 11, s = m & 2047;
            float* dp = dst + (((size_t)(b * H_ + h) * S_) + s) * HD_ + hd;
#pragma unroll
            for (int j = 0; j < 8; ++j) dp[j] = acc[i][j] + bp2[j];
        }
    }
}

// ---------------------------------------------------------------------------
// feat_importance[i] = sigmoid(mean_d q[i,d])
// ---------------------------------------------------------------------------
__global__ void fi_kernel()
{
    int i = blockIdx.x * blockDim.x + threadIdx.x;
    if (i >= NBH * S_) return;
    const float4* q = (const float4*)(g_q + (size_t)i * HD_);
    float s = 0.f;
#pragma unroll
    for (int u = 0; u < 16; ++u) {
        float4 v = q[u];
        s += v.x + v.y + v.z + v.w;
    }
    float mval = s * (1.f / 64.f);
    g_fi[i] = 1.f / (1.f + expf(-mval));
}

// ---------------------------------------------------------------------------
// Register top-5 (sorted desc) insert; fully unrolled -> stays in registers.
// ---------------------------------------------------------------------------
__device__ __forceinline__ void top5_ins(float (&v)[5], int (&ix)[5], float s, int si)
{
    if (s <= v[4]) return;
    v[4] = s; ix[4] = si;
#pragma unroll
    for (int u = 4; u > 0; --u) {
        if (v[u] > v[u - 1]) {
            float tv = v[u]; v[u] = v[u - 1]; v[u - 1] = tv;
            int   ti = ix[u]; ix[u] = ix[u - 1]; ix[u - 1] = ti;
        }
    }
}

// ---------------------------------------------------------------------------
// Fused scores + top-5 + sparse local mask + softmax + attn scatter + ctx.
// One block: 64 queries of one (b,h); streams all 2048 keys in 128-wide tiles.
// ---------------------------------------------------------------------------
__global__ __launch_bounds__(256)
void attn_kernel(float* __restrict__ out_attn)   // may be nullptr
{
    __shared__ float shQ[64][64];                 // [d][q] transposed
    __shared__ __align__(16) char ubuf[32768];    // shK during compute; merge buf after
    float* shK = (float*)ubuf;                    // [64][128] d-major

    const int tid = threadIdx.x;
    const int tx = tid & 15, ty = tid >> 4;
    const int bh = blockIdx.y;
    const int q0 = blockIdx.x << 6;

    const float* qb = g_q + ((size_t)bh * S_ + q0) * HD_;
    const float* kb = g_k + (size_t)bh * S_ * HD_;

    // stage Q tile (transposed into shQ[d][q]; STS conflict-free: bank = q%32)
#pragma unroll
    for (int r = 0; r < 4; ++r) {
        int e = tid + (r << 8);
        int q = e & 63, c4 = e >> 6;
        float4 v = *(const float4*)(qb + (size_t)q * HD_ + (c4 << 2));
        shQ[(c4 << 2) + 0][q] = v.x;
        shQ[(c4 << 2) + 1][q] = v.y;
        shQ[(c4 << 2) + 2][q] = v.z;
        shQ[(c4 << 2) + 3][q] = v.w;
    }

    float t5v[4][5]; int t5i[4][5];
#pragma unroll
    for (int i = 0; i < 4; ++i)
#pragma unroll
        for (int u = 0; u < 5; ++u) { t5v[i][u] = -INFINITY; t5i[i][u] = 0; }

    for (int kt = 0; kt < 16; ++kt) {
        const float* ktp = kb + ((size_t)kt << 7) * HD_;
        __syncthreads();   // prior tile's readers done (first iter: orders shQ too)
#pragma unroll
        for (int r = 0; r < 8; ++r) {
            int e = tid + (r << 8);
            int key = e & 127, c4 = e >> 7;
            float4 v = *(const float4*)(ktp + (size_t)key * HD_ + (c4 << 2));
            shK[((c4 << 2) + 0) * 128 + key] = v.x;
            shK[((c4 << 2) + 1) * 128 + key] = v.y;
            shK[((c4 << 2) + 2) * 128 + key] = v.z;
            shK[((c4 << 2) + 3) * 128 + key] = v.w;
        }
        __syncthreads();

        float acc[4][8];
#pragma unroll
        for (int i = 0; i < 4; ++i)
#pragma unroll
            for (int j = 0; j < 8; ++j) acc[i][j] = 0.f;

#pragma unroll 4
        for (int d = 0; d < 64; ++d) {
            float4 qv = *(const float4*)&shQ[d][ty << 2];
            const float* kp = shK + d * 128 + (tx << 3);
            float4 k0 = *(const float4*)kp;
            float4 k1 = *(const float4*)(kp + 4);
            float am[4] = {qv.x, qv.y, qv.z, qv.w};
            float bn[8] = {k0.x,k0.y,k0.z,k0.w,k1.x,k1.y,k1.z,k1.w};
#pragma unroll
            for (int i = 0; i < 4; ++i)
#pragma unroll
                for (int j = 0; j < 8; ++j)
                    acc[i][j] += am[i] * bn[j];
        }

        int kg0 = (kt << 7) + (tx << 3);
#pragma unroll
        for (int i = 0; i < 4; ++i)
#pragma unroll
            for (int j = 0; j < 8; ++j)
                top5_ins(t5v[i], t5i[i], acc[i][j], kg0 + j);
    }
    __syncthreads();

    // merge buffers overlay shK region (layout: 20480 + 10240 + 1280 + 640 <= 32768)
    float*          mb_v = (float*)ubuf;                     // [64][16][5]
    unsigned short* mb_i = (unsigned short*)(ubuf + 20480);  // [64][16][5]
    float*          pw   = (float*)(ubuf + 30720);           // [64][5]
    unsigned short* pidx = (unsigned short*)(ubuf + 32000);  // [64][5]

#pragma unroll
    for (int i = 0; i < 4; ++i) {
        int q = (ty << 2) + i;
#pragma unroll
        for (int u = 0; u < 5; ++u) {
            mb_v[(q * 16 + tx) * 5 + u] = t5v[i][u];
            mb_i[(q * 16 + tx) * 5 + u] = (unsigned short)t5i[i][u];
        }
    }
    __syncthreads();

    if (tid < 64) {
        const int q = tid;
        const int r = q0 + q;
        float v[5]; int id[5];
#pragma unroll
        for (int u = 0; u < 5; ++u) { v[u] = -INFINITY; id[u] = 0; }
        for (int t = 0; t < 16; ++t) {
#pragma unroll
            for (int u = 0; u < 5; ++u)
                top5_ins(v, id, mb_v[(q * 16 + t) * 5 + u], (int)mb_i[(q * 16 + t) * 5 + u]);
        }

        // local sparse-window mask: only |r-c|<=3 "covered" pairs can fail it
        bool kp[5];
#pragma unroll
        for (int i = 0; i < 5; ++i) {
            int c = id[i];
            int mn = min(r, c), mx = max(r, c);
            int ow = mn & ~1; if (ow > 2044) ow = 2044;
            bool keep = true;
            if (mx <= ow + 3) {
                float st[4];
#pragma unroll
                for (int t = 0; t < 4; ++t) {
                    const float* kr = kb + (size_t)(ow + t) * HD_;
                    float s = 0.f;
                    for (int d = 0; d < 64; ++d) s += shQ[d][q] * kr[d];
                    st[t] = s;
                }
                // 3rd-largest of 4 == 2nd-smallest of 4
                float mn01 = fminf(st[0], st[1]), mx01 = fmaxf(st[0], st[1]);
                float mn23 = fminf(st[2], st[3]), mx23 = fmaxf(st[2], st[3]);
                float thr = fminf(fmaxf(mn01, mn23), fminf(mx01, mx23));
                int ci = c - ow;
                float cv = (ci == 0) ? st[0] : (ci == 1) ? st[1] : (ci == 2) ? st[2] : st[3];
                keep = (cv >= thr);
            }
            kp[i] = keep;
        }

        // softmax over kept candidates (row max is provably always kept)
        float sm = -INFINITY;
#pragma unroll
        for (int i = 0; i < 5; ++i) if (kp[i]) sm = fmaxf(sm, v[i]);
        sm *= 0.125f;   // exact /8 of max == max of (raw/8)
        float p[5]; float sum = 0.f;
#pragma unroll
        for (int i = 0; i < 5; ++i) {
            p[i] = kp[i] ? expf(v[i] * 0.125f - sm) : 0.f;
            sum += p[i];
        }
        float inv = 1.f / sum;
#pragma unroll
        for (int i = 0; i < 5; ++i) {
            if (kp[i]) {
                float pi = p[i] * inv;
                int c = id[i];
                if (out_attn) out_attn[((size_t)bh * S_ + r) * S_ + c] = pi;
                pw[q * 5 + i] = pi * g_fi[(size_t)bh * S_ + c];
                pidx[q * 5 + i] = (unsigned short)c;
            } else {
                pw[q * 5 + i] = 0.f;
                pidx[q * 5 + i] = 0;
            }
        }
    }
    __syncthreads();

    // sparse ctx: out[q,:] = sum_i pw * v[c_i,:]   (4 threads per query, 16 dims each)
    {
        const int q = tid >> 2;
        const int dq = (tid & 3) << 4;
        float a[16];
#pragma unroll
        for (int u = 0; u < 16; ++u) a[u] = 0.f;
        const float* vb = g_v + (size_t)bh * S_ * HD_;
#pragma unroll
        for (int i = 0; i < 5; ++i) {
            float w = pw[q * 5 + i];
            int c = pidx[q * 5 + i];
            const float4* vr = (const float4*)(vb + (size_t)c * HD_ + dq);
#pragma unroll
            for (int u2 = 0; u2 < 4; ++u2) {
                float4 vv = vr[u2];
                a[u2 * 4 + 0] += w * vv.x;
                a[u2 * 4 + 1] += w * vv.y;
                a[u2 * 4 + 2] += w * vv.z;
                a[u2 * 4 + 3] += w * vv.w;
            }
        }
        int b = bh >> 3, h = bh & 7;
        float* dp = g_ctx + (size_t)(b * S_ + q0 + q) * D_ + (h << 6) + dq;
#pragma unroll
        for (int u2 = 0; u2 < 4; ++u2)
            *(float4*)(dp + (u2 << 2)) =
                make_float4(a[u2 * 4 + 0], a[u2 * 4 + 1], a[u2 * 4 + 2], a[u2 * 4 + 3]);
    }
}

// ---------------------------------------------------------------------------
extern "C" void kernel_launch(void* const* d_in, const int* in_sizes, int n_in,
                              void* d_out, int out_size)
{
    const float* x      = (const float*)d_in[0];
    const float* w_qkv  = (const float*)d_in[1];
    const float* b_qkv  = (const float*)d_in[2];
    const float* w_proj = (const float*)d_in[3];
    const float* b_proj = (const float*)d_in[4];
    float* out = (float*)d_out;

    const size_t nproj = (size_t)B_ * S_ * D_;          // 2,097,152
    const size_t nattn = (size_t)NBH * S_ * S_;         // 67,108,864
    float* out_attn = ((size_t)out_size >= nproj + nattn) ? (out + nproj) : nullptr;

    // 1) fused QKV projection -> head-layout q/k/v
    sgemm128<<<dim3(12, 32), 256>>>(x, w_qkv, b_qkv, nullptr, B_ * S_, 3 * D_, D_, 1);
    // 2) feature importance per (b,h,s)
    fi_kernel<<<(NBH * S_ + 255) / 256, 256>>>();
    // 3) attn map is exact-zero off the sparse mask: memset + scatter
    if (out_attn) cudaMemsetAsync(out_attn, 0, nattn * sizeof(float), 0);
    // 4) fused scores / top-5 / mask / softmax / sparse ctx
    attn_kernel<<<dim3(S_ / 64, NBH), 256>>>(out_attn);
    // 5) output projection
    sgemm128<<<dim3(4, 32), 256>>>(nullptr, w_proj, b_proj, out, B_ * S_, D_, D_, 2);
}

// round 6
// speedup vs baseline: 1.1119x; 1.1119x over previous
#include <cuda_runtime.h>
#include <math.h>

#define B_  2
#define S_  2048
#define D_  512
#define H_  8
#define HD_ 64
#define NBH 16   // B_*H_

// Scratch (static __device__ — no allocations allowed)
__device__ float g_q[(size_t)NBH * S_ * HD_];
__device__ float g_k[(size_t)NBH * S_ * HD_];
__device__ float g_v[(size_t)NBH * S_ * HD_];
__device__ float g_fi[(size_t)NBH * S_];
__device__ float g_ctx[(size_t)B_ * S_ * D_];

// ---------------------------------------------------------------------------
// Pipelined fp32 GEMM: 128(M) x 64(N) x 16(K) tiles, 256 threads, 8x4 micro.
// k-ascending single-accumulator order == sgemm128 (bitwise-identical results).
// mode 1: QKV epilogue -> scatter to g_q/g_k/g_v head layout
// mode 2: A := g_ctx, C = A@B + bias (proj)
// ---------------------------------------------------------------------------
__global__ __launch_bounds__(256)
void sgemm_pipe(const float* __restrict__ A, const float* __restrict__ Bm,
                const float* __restrict__ bias, float* __restrict__ C,
                int M, int N, int K, int mode)
{
    if (mode == 2) A = g_ctx;
    __shared__ float As[16][132];   // transposed: As[k][m], padded
    __shared__ float Bs[16][64];

    const int tid = threadIdx.x;
    const int tx = tid & 15, ty = tid >> 4;
    const int m0 = blockIdx.y << 7, n0 = blockIdx.x << 6;

    const int arow = tid >> 1;            // 0..127
    const int ac   = (tid & 1) << 3;      // k base 0 or 8
    const int brow = tid >> 4;            // 0..15
    const int bc   = (tid & 15) << 2;     // 0..60

    const float* Ap = A  + (size_t)(m0 + arow) * K + ac;
    const float* Bp = Bm + (size_t)brow * N + n0 + bc;

    float acc[8][4];
#pragma unroll
    for (int i = 0; i < 8; ++i)
#pragma unroll
        for (int j = 0; j < 4; ++j) acc[i][j] = 0.f;

    float4 pa0 = *(const float4*)(Ap);
    float4 pa1 = *(const float4*)(Ap + 4);
    float4 pb  = *(const float4*)(Bp);

    const int ty8 = ty << 3, tx4 = tx << 2;

    for (int k0 = 0; k0 < K; k0 += 16) {
        __syncthreads();
        As[ac + 0][arow] = pa0.x;
        As[ac + 1][arow] = pa0.y;
        As[ac + 2][arow] = pa0.z;
        As[ac + 3][arow] = pa0.w;
        As[ac + 4][arow] = pa1.x;
        As[ac + 5][arow] = pa1.y;
        As[ac + 6][arow] = pa1.z;
        As[ac + 7][arow] = pa1.w;
        *(float4*)&Bs[brow][bc] = pb;
        __syncthreads();
        if (k0 + 16 < K) {
            pa0 = *(const float4*)(Ap + k0 + 16);
            pa1 = *(const float4*)(Ap + k0 + 20);
            pb  = *(const float4*)(Bp + (size_t)(k0 + 16) * N);
        }
#pragma unroll
        for (int kk = 0; kk < 16; ++kk) {
            float4 a0 = *(const float4*)&As[kk][ty8];
            float4 a1 = *(const float4*)&As[kk][ty8 + 4];
            float4 bv = *(const float4*)&Bs[kk][tx4];
            float am[8] = {a0.x,a0.y,a0.z,a0.w,a1.x,a1.y,a1.z,a1.w};
            float bn[4] = {bv.x,bv.y,bv.z,bv.w};
#pragma unroll
            for (int i = 0; i < 8; ++i)
#pragma unroll
                for (int j = 0; j < 4; ++j)
                    acc[i][j] += am[i] * bn[j];
        }
    }

    const int n_base = n0 + tx4;
    if (mode != 1) {
        const float* bp2 = bias + n_base;
        float4 bb = make_float4(bp2[0], bp2[1], bp2[2], bp2[3]);
#pragma unroll
        for (int i = 0; i < 8; ++i) {
            int m = m0 + ty8 + i;
            float4 v = make_float4(acc[i][0] + bb.x, acc[i][1] + bb.y,
                                   acc[i][2] + bb.z, acc[i][3] + bb.w);
            *(float4*)(C + (size_t)m * N + n_base) = v;
        }
    } else {
        // qkv scatter: n -> (q/k/v, head, hd); 4 consecutive n within one head
        int t3 = n_base >> 9;            // 0:q 1:k 2:v
        int cc = n_base & 511;
        int h = cc >> 6, hd = cc & 63;
        float* dst = (t3 == 0) ? g_q : (t3 == 1) ? g_k : g_v;
        const float* bp2 = bias + n_base;
        float4 bb = make_float4(bp2[0], bp2[1], bp2[2], bp2[3]);
#pragma unroll
        for (int i = 0; i < 8; ++i) {
            int m = m0 + ty8 + i;
            int b = m >> 11, s = m & 2047;
            size_t off = (((size_t)(b * H_ + h) * S_) + s) * HD_ + hd;
            *(float4*)(dst + off) = make_float4(acc[i][0] + bb.x, acc[i][1] + bb.y,
                                                acc[i][2] + bb.z, acc[i][3] + bb.w);
        }
    }
}

// ---------------------------------------------------------------------------
// feat_importance[i] = sigmoid(mean_d q[i,d])
// ---------------------------------------------------------------------------
__global__ void fi_kernel()
{
    int i = blockIdx.x * blockDim.x + threadIdx.x;
    if (i >= NBH * S_) return;
    const float4* q = (const float4*)(g_q + (size_t)i * HD_);
    float s = 0.f;
#pragma unroll
    for (int u = 0; u < 16; ++u) {
        float4 v = q[u];
        s += v.x + v.y + v.z + v.w;
    }
    float mval = s * (1.f / 64.f);
    g_fi[i] = 1.f / (1.f + expf(-mval));
}

// ---------------------------------------------------------------------------
// Register top-5 (sorted desc) insert; fully unrolled -> stays in registers.
// ---------------------------------------------------------------------------
__device__ __forceinline__ void top5_ins(float (&v)[5], int (&ix)[5], float s, int si)
{
    if (s <= v[4]) return;
    v[4] = s; ix[4] = si;
#pragma unroll
    for (int u = 4; u > 0; --u) {
        if (v[u] > v[u - 1]) {
            float tv = v[u]; v[u] = v[u - 1]; v[u - 1] = tv;
            int   ti = ix[u]; ix[u] = ix[u - 1]; ix[u - 1] = ti;
        }
    }
}

// ---------------------------------------------------------------------------
// R1-proven fused scores + top-5 + sparse local mask + softmax + attn scatter
// + sparse ctx. One block: 64 queries of one (b,h); streams 2048 keys in
// 128-wide tiles. Zero-fills its own 64 attn rows (replaces serial memset).
// ---------------------------------------------------------------------------
__global__ __launch_bounds__(256)
void attn_kernel(float* __restrict__ out_attn)   // may be nullptr
{
    __shared__ float shQ[64][64];                 // [d][q] transposed
    __shared__ __align__(16) char ubuf[32768];    // shK during compute; merge buf after
    float* shK = (float*)ubuf;                    // [64][128] d-major

    const int tid = threadIdx.x;
    const int tx = tid & 15, ty = tid >> 4;
    const int bh = blockIdx.y;
    const int q0 = blockIdx.x << 6;

    // in-kernel zero-fill of this block's 64 attn rows (overlaps with compute)
    if (out_attn) {
        float4 z4 = make_float4(0.f, 0.f, 0.f, 0.f);
        float4* zp = (float4*)(out_attn + ((size_t)bh * S_ + q0) * S_);
        for (int i = tid; i < 64 * S_ / 4; i += 256) zp[i] = z4;
    }

    const float* qb = g_q + ((size_t)bh * S_ + q0) * HD_;
    const float* kb = g_k + (size_t)bh * S_ * HD_;

    // stage Q tile (transposed into shQ[d][q]; STS conflict-free: bank = q%32)
#pragma unroll
    for (int r = 0; r < 4; ++r) {
        int e = tid + (r << 8);
        int q = e & 63, c4 = e >> 6;
        float4 v = *(const float4*)(qb + (size_t)q * HD_ + (c4 << 2));
        shQ[(c4 << 2) + 0][q] = v.x;
        shQ[(c4 << 2) + 1][q] = v.y;
        shQ[(c4 << 2) + 2][q] = v.z;
        shQ[(c4 << 2) + 3][q] = v.w;
    }

    float t5v[4][5]; int t5i[4][5];
#pragma unroll
    for (int i = 0; i < 4; ++i)
#pragma unroll
        for (int u = 0; u < 5; ++u) { t5v[i][u] = -INFINITY; t5i[i][u] = 0; }

    for (int kt = 0; kt < 16; ++kt) {
        const float* ktp = kb + ((size_t)kt << 7) * HD_;
        __syncthreads();   // prior tile's readers done (first iter: orders shQ too)
#pragma unroll
        for (int r = 0; r < 8; ++r) {
            int e = tid + (r << 8);
            int key = e & 127, c4 = e >> 7;
            float4 v = *(const float4*)(ktp + (size_t)key * HD_ + (c4 << 2));
            shK[((c4 << 2) + 0) * 128 + key] = v.x;
            shK[((c4 << 2) + 1) * 128 + key] = v.y;
            shK[((c4 << 2) + 2) * 128 + key] = v.z;
            shK[((c4 << 2) + 3) * 128 + key] = v.w;
        }
        __syncthreads();

        float acc[4][8];
#pragma unroll
        for (int i = 0; i < 4; ++i)
#pragma unroll
            for (int j = 0; j < 8; ++j) acc[i][j] = 0.f;

#pragma unroll 4
        for (int d = 0; d < 64; ++d) {
            float4 qv = *(const float4*)&shQ[d][ty << 2];
            const float* kp = shK + d * 128 + (tx << 3);
            float4 k0 = *(const float4*)kp;
            float4 k1 = *(const float4*)(kp + 4);
            float am[4] = {qv.x, qv.y, qv.z, qv.w};
            float bn[8] = {k0.x,k0.y,k0.z,k0.w,k1.x,k1.y,k1.z,k1.w};
#pragma unroll
            for (int i = 0; i < 4; ++i)
#pragma unroll
                for (int j = 0; j < 8; ++j)
                    acc[i][j] += am[i] * bn[j];
        }

        int kg0 = (kt << 7) + (tx << 3);
#pragma unroll
        for (int i = 0; i < 4; ++i)
#pragma unroll
            for (int j = 0; j < 8; ++j)
                top5_ins(t5v[i], t5i[i], acc[i][j], kg0 + j);
    }
    __syncthreads();

    // merge buffers overlay shK region (layout: 20480 + 10240 + 1280 + 640 <= 32768)
    float*          mb_v = (float*)ubuf;                     // [64][16][5]
    unsigned short* mb_i = (unsigned short*)(ubuf + 20480);  // [64][16][5]
    float*          pw   = (float*)(ubuf + 30720);           // [64][5]
    unsigned short* pidx = (unsigned short*)(ubuf + 32000);  // [64][5]

#pragma unroll
    for (int i = 0; i < 4; ++i) {
        int q = (ty << 2) + i;
#pragma unroll
        for (int u = 0; u < 5; ++u) {
            mb_v[(q * 16 + tx) * 5 + u] = t5v[i][u];
            mb_i[(q * 16 + tx) * 5 + u] = (unsigned short)t5i[i][u];
        }
    }
    __syncthreads();

    if (tid < 64) {
        const int q = tid;
        const int r = q0 + q;
        float v[5]; int id[5];
#pragma unroll
        for (int u = 0; u < 5; ++u) { v[u] = -INFINITY; id[u] = 0; }
        for (int t = 0; t < 16; ++t) {
#pragma unroll
            for (int u = 0; u < 5; ++u)
                top5_ins(v, id, mb_v[(q * 16 + t) * 5 + u], (int)mb_i[(q * 16 + t) * 5 + u]);
        }

        // local sparse-window mask: only |r-c|<=3 "covered" pairs can fail it
        bool kp[5];
#pragma unroll
        for (int i = 0; i < 5; ++i) {
            int c = id[i];
            int mn = min(r, c), mx = max(r, c);
            int ow = mn & ~1; if (ow > 2044) ow = 2044;
            bool keep = true;
            if (mx <= ow + 3) {
                float st[4];
#pragma unroll
                for (int t = 0; t < 4; ++t) {
                    const float* kr = kb + (size_t)(ow + t) * HD_;
                    float s = 0.f;
                    for (int d = 0; d < 64; ++d) s += shQ[d][q] * kr[d];
                    st[t] = s;
                }
                // 3rd-largest of 4 == 2nd-smallest of 4
                float mn01 = fminf(st[0], st[1]), mx01 = fmaxf(st[0], st[1]);
                float mn23 = fminf(st[2], st[3]), mx23 = fmaxf(st[2], st[3]);
                float thr = fminf(fmaxf(mn01, mn23), fminf(mx01, mx23));
                int ci = c - ow;
                float cv = (ci == 0) ? st[0] : (ci == 1) ? st[1] : (ci == 2) ? st[2] : st[3];
                keep = (cv >= thr);
            }
            kp[i] = keep;
        }

        // softmax over kept candidates (row max is provably always kept)
        float sm = -INFINITY;
#pragma unroll
        for (int i = 0; i < 5; ++i) if (kp[i]) sm = fmaxf(sm, v[i]);
        sm *= 0.125f;   // exact /8 of max == max of (raw/8)
        float p[5]; float sum = 0.f;
#pragma unroll
        for (int i = 0; i < 5; ++i) {
            p[i] = kp[i] ? expf(v[i] * 0.125f - sm) : 0.f;
            sum += p[i];
        }
        float inv = 1.f / sum;
#pragma unroll
        for (int i = 0; i < 5; ++i) {
            if (kp[i]) {
                float pi = p[i] * inv;
                int c = id[i];
                if (out_attn) out_attn[((size_t)bh * S_ + r) * S_ + c] = pi;
                pw[q * 5 + i] = pi * g_fi[(size_t)bh * S_ + c];
                pidx[q * 5 + i] = (unsigned short)c;
            } else {
                pw[q * 5 + i] = 0.f;
                pidx[q * 5 + i] = 0;
            }
        }
    }
    __syncthreads();

    // sparse ctx: out[q,:] = sum_i pw * v[c_i,:]   (4 threads per query, 16 dims each)
    {
        const int q = tid >> 2;
        const int dq = (tid & 3) << 4;
        float a[16];
#pragma unroll
        for (int u = 0; u < 16; ++u) a[u] = 0.f;
        const float* vb = g_v + (size_t)bh * S_ * HD_;
#pragma unroll
        for (int i = 0; i < 5; ++i) {
            float w = pw[q * 5 + i];
            int c = pidx[q * 5 + i];
            const float4* vr = (const float4*)(vb + (size_t)c * HD_ + dq);
#pragma unroll
            for (int u2 = 0; u2 < 4; ++u2) {
                float4 vv = vr[u2];
                a[u2 * 4 + 0] += w * vv.x;
                a[u2 * 4 + 1] += w * vv.y;
                a[u2 * 4 + 2] += w * vv.z;
                a[u2 * 4 + 3] += w * vv.w;
            }
        }
        int b = bh >> 3, h = bh & 7;
        float* dp = g_ctx + (size_t)(b * S_ + q0 + q) * D_ + (h << 6) + dq;
#pragma unroll
        for (int u2 = 0; u2 < 4; ++u2)
            *(float4*)(dp + (u2 << 2)) =
                make_float4(a[u2 * 4 + 0], a[u2 * 4 + 1], a[u2 * 4 + 2], a[u2 * 4 + 3]);
    }
}

// ---------------------------------------------------------------------------
extern "C" void kernel_launch(void* const* d_in, const int* in_sizes, int n_in,
                              void* d_out, int out_size)
{
    const float* x      = (const float*)d_in[0];
    const float* w_qkv  = (const float*)d_in[1];
    const float* b_qkv  = (const float*)d_in[2];
    const float* w_proj = (const float*)d_in[3];
    const float* b_proj = (const float*)d_in[4];
    float* out = (float*)d_out;

    const size_t nproj = (size_t)B_ * S_ * D_;          // 2,097,152
    const size_t nattn = (size_t)NBH * S_ * S_;         // 67,108,864
    float* out_attn = ((size_t)out_size >= nproj + nattn) ? (out + nproj) : nullptr;

    // 1) fused QKV projection -> head-layout q/k/v (pipelined GEMM)
    sgemm_pipe<<<dim3(24, 32), 256>>>(x, w_qkv, b_qkv, nullptr, B_ * S_, 3 * D_, D_, 1);
    // 2) feature importance per (b,h,s)
    fi_kernel<<<128, 256>>>();
    // 3) fused scores / top-5 / mask / softmax / sparse ctx (self zero-filling)
    attn_kernel<<<dim3(S_ / 64, NBH), 256>>>(out_attn);
    // 4) output projection
    sgemm_pipe<<<dim3(8, 32), 256>>>(nullptr, w_proj, b_proj, out, B_ * S_, D_, D_, 2);
}

// round 7
// speedup vs baseline: 1.6213x; 1.4582x over previous
#include <cuda_runtime.h>
#include <cuda_bf16.h>
#include <math.h>

#define B_  2
#define S_  2048
#define D_  512
#define H_  8
#define HD_ 64
#define NBH 16   // B_*H_

// Scratch (static __device__ — no allocations allowed)
__device__ float g_q[(size_t)NBH * S_ * HD_];
__device__ float g_k[(size_t)NBH * S_ * HD_];
__device__ float g_v[(size_t)NBH * S_ * HD_];
__device__ __nv_bfloat16 g_qh[(size_t)NBH * S_ * HD_];
__device__ __nv_bfloat16 g_kh[(size_t)NBH * S_ * HD_];
__device__ float g_fi[(size_t)NBH * S_];
__device__ float g_ctx[(size_t)B_ * S_ * D_];

// ---------------------------------------------------------------------------
// Pipelined fp32 GEMM: 128(M) x 64(N) x 16(K) tiles, 256 threads, 8x4 micro.
// mode 1: QKV epilogue -> scatter to g_q/g_k/g_v (+ bf16 q,k planes)
// mode 2: A := g_ctx, C = A@B + bias (proj)
// ---------------------------------------------------------------------------
__global__ __launch_bounds__(256)
void sgemm_pipe(const float* __restrict__ A, const float* __restrict__ Bm,
                const float* __restrict__ bias, float* __restrict__ C,
                int M, int N, int K, int mode)
{
    if (mode == 2) A = g_ctx;
    __shared__ float As[16][132];   // transposed: As[k][m], padded
    __shared__ float Bs[16][64];

    const int tid = threadIdx.x;
    const int tx = tid & 15, ty = tid >> 4;
    const int m0 = blockIdx.y << 7, n0 = blockIdx.x << 6;

    const int arow = tid >> 1;            // 0..127
    const int ac   = (tid & 1) << 3;      // k base 0 or 8
    const int brow = tid >> 4;            // 0..15
    const int bc   = (tid & 15) << 2;     // 0..60

    const float* Ap = A  + (size_t)(m0 + arow) * K + ac;
    const float* Bp = Bm + (size_t)brow * N + n0 + bc;

    float acc[8][4];
#pragma unroll
    for (int i = 0; i < 8; ++i)
#pragma unroll
        for (int j = 0; j < 4; ++j) acc[i][j] = 0.f;

    float4 pa0 = *(const float4*)(Ap);
    float4 pa1 = *(const float4*)(Ap + 4);
    float4 pb  = *(const float4*)(Bp);

    const int ty8 = ty << 3, tx4 = tx << 2;

    for (int k0 = 0; k0 < K; k0 += 16) {
        __syncthreads();
        As[ac + 0][arow] = pa0.x;
        As[ac + 1][arow] = pa0.y;
        As[ac + 2][arow] = pa0.z;
        As[ac + 3][arow] = pa0.w;
        As[ac + 4][arow] = pa1.x;
        As[ac + 5][arow] = pa1.y;
        As[ac + 6][arow] = pa1.z;
        As[ac + 7][arow] = pa1.w;
        *(float4*)&Bs[brow][bc] = pb;
        __syncthreads();
        if (k0 + 16 < K) {
            pa0 = *(const float4*)(Ap + k0 + 16);
            pa1 = *(const float4*)(Ap + k0 + 20);
            pb  = *(const float4*)(Bp + (size_t)(k0 + 16) * N);
        }
#pragma unroll
        for (int kk = 0; kk < 16; ++kk) {
            float4 a0 = *(const float4*)&As[kk][ty8];
            float4 a1 = *(const float4*)&As[kk][ty8 + 4];
            float4 bv = *(const float4*)&Bs[kk][tx4];
            float am[8] = {a0.x,a0.y,a0.z,a0.w,a1.x,a1.y,a1.z,a1.w};
            float bn[4] = {bv.x,bv.y,bv.z,bv.w};
#pragma unroll
            for (int i = 0; i < 8; ++i)
#pragma unroll
                for (int j = 0; j < 4; ++j)
                    acc[i][j] += am[i] * bn[j];
        }
    }

    const int n_base = n0 + tx4;
    if (mode != 1) {
        const float* bp2 = bias + n_base;
        float4 bb = make_float4(bp2[0], bp2[1], bp2[2], bp2[3]);
#pragma unroll
        for (int i = 0; i < 8; ++i) {
            int m = m0 + ty8 + i;
            float4 v = make_float4(acc[i][0] + bb.x, acc[i][1] + bb.y,
                                   acc[i][2] + bb.z, acc[i][3] + bb.w);
            *(float4*)(C + (size_t)m * N + n_base) = v;
        }
    } else {
        // qkv scatter: n -> (q/k/v, head, hd); 4 consecutive n within one head
        int t3 = n_base >> 9;            // 0:q 1:k 2:v
        int cc = n_base & 511;
        int h = cc >> 6, hd = cc & 63;
        float* dst = (t3 == 0) ? g_q : (t3 == 1) ? g_k : g_v;
        __nv_bfloat16* dsth = (t3 == 0) ? g_qh : (t3 == 1) ? g_kh : nullptr;
        const float* bp2 = bias + n_base;
        float4 bb = make_float4(bp2[0], bp2[1], bp2[2], bp2[3]);
#pragma unroll
        for (int i = 0; i < 8; ++i) {
            int m = m0 + ty8 + i;
            int b = m >> 11, s = m & 2047;
            size_t off = (((size_t)(b * H_ + h) * S_) + s) * HD_ + hd;
            float v0 = acc[i][0] + bb.x, v1 = acc[i][1] + bb.y;
            float v2 = acc[i][2] + bb.z, v3 = acc[i][3] + bb.w;
            *(float4*)(dst + off) = make_float4(v0, v1, v2, v3);
            if (dsth) {
                unsigned p0 = (unsigned)__bfloat16_as_ushort(__float2bfloat16_rn(v0)) |
                              ((unsigned)__bfloat16_as_ushort(__float2bfloat16_rn(v1)) << 16);
                unsigned p1 = (unsigned)__bfloat16_as_ushort(__float2bfloat16_rn(v2)) |
                              ((unsigned)__bfloat16_as_ushort(__float2bfloat16_rn(v3)) << 16);
                *(uint2*)(dsth + off) = make_uint2(p0, p1);
            }
        }
    }
}

// ---------------------------------------------------------------------------
__global__ void fi_kernel()
{
    int i = blockIdx.x * blockDim.x + threadIdx.x;
    if (i >= NBH * S_) return;
    const float4* q = (const float4*)(g_q + (size_t)i * HD_);
    float s = 0.f;
#pragma unroll
    for (int u = 0; u < 16; ++u) {
        float4 v = q[u];
        s += v.x + v.y + v.z + v.w;
    }
    float mval = s * (1.f / 64.f);
    g_fi[i] = 1.f / (1.f + expf(-mval));
}

// ---------------------------------------------------------------------------
__device__ __forceinline__ void ldsm4(unsigned* r, unsigned saddr)
{
    asm volatile("ldmatrix.sync.aligned.m8n8.x4.shared.b16 {%0,%1,%2,%3}, [%4];"
                 : "=r"(r[0]), "=r"(r[1]), "=r"(r[2]), "=r"(r[3]) : "r"(saddr));
}

__device__ __forceinline__ void mma_bf16(float* c, const unsigned* a, const unsigned* b)
{
    asm volatile("mma.sync.aligned.m16n8k16.row.col.f32.bf16.bf16.f32 "
                 "{%0,%1,%2,%3},{%4,%5,%6,%7},{%8,%9},{%0,%1,%2,%3};"
                 : "+f"(c[0]), "+f"(c[1]), "+f"(c[2]), "+f"(c[3])
                 : "r"(a[0]), "r"(a[1]), "r"(a[2]), "r"(a[3]),
                   "r"(b[0]), "r"(b[1]));
}

// Sequential d-ascending single-accumulator FFMA chain — bitwise identical to
// the R1 kernel's score arithmetic (acc += a[d]*b[d], d = 0..63 in order).
// This is load-bearing: it reproduces R1's resolution of near-tied scores.
__device__ __forceinline__ float dot64_seq(const float* __restrict__ a,
                                           const float* __restrict__ b)
{
    const float4* A4 = (const float4*)a;
    const float4* B4 = (const float4*)b;
    float s = 0.f;
#pragma unroll
    for (int i = 0; i < 16; ++i) {
        float4 x = A4[i], y = B4[i];
        s = __fmaf_rn(x.x, y.x, s);
        s = __fmaf_rn(x.y, y.y, s);
        s = __fmaf_rn(x.z, y.z, s);
        s = __fmaf_rn(x.w, y.w, s);
    }
    return s;
}

// unconditional sorted-desc top-8 insert; caller pre-checks v > tv[7]
__device__ __forceinline__ void ins8(float* tv, int* ti, float v, int idx)
{
    tv[7] = v; ti[7] = idx;
#pragma unroll
    for (int u = 7; u > 0; --u) {
        if (tv[u] > tv[u - 1]) {
            float a = tv[u]; tv[u] = tv[u - 1]; tv[u - 1] = a;
            int   b = ti[u]; ti[u] = ti[u - 1]; ti[u - 1] = b;
        }
    }
}

// ---------------------------------------------------------------------------
// Tensor-core approx scores -> smem (explicit coords) -> scalar top-8 per
// half-row -> EXACT sequential-fp32 rescore of 16 -> top-5 -> window mask ->
// softmax -> attn scatter + sparse ctx.
// Block: 128 queries of one (b,h); 256 threads = 8 warps; 64-key tiles.
// ---------------------------------------------------------------------------
__global__ __launch_bounds__(256)
void attn_mma2(float* __restrict__ out_attn)
{
    __shared__ float shS[64 * 132];                   // [key][query] scores; overlaid later
    __shared__ __align__(16) unsigned char shK[8192]; // 64 keys x 128B, swizzled
    __shared__ float spw[128][5];
    __shared__ unsigned short spidx[128][5];

    const int tid = threadIdx.x;
    const int w = tid >> 5, lane = tid & 31;
    const int bh = blockIdx.y;
    const int qblk = blockIdx.x << 7;

    // in-kernel zero-fill of this block's attn rows (overlaps the mma loop)
    if (out_attn) {
        float4 z4 = make_float4(0.f, 0.f, 0.f, 0.f);
        float4* zp = (float4*)(out_attn + ((size_t)bh * S_ + qblk) * S_);
        for (int i = tid; i < 128 * S_ / 4; i += 256) zp[i] = z4;
    }

    const __nv_bfloat16* qh = g_qh + ((size_t)bh * S_ + qblk) * HD_;
    const __nv_bfloat16* kh = g_kh + (size_t)bh * S_ * HD_;

    // ---- A fragments for this warp's 16 rows (PTX m16n8k16 A layout) ----
    unsigned Af[4][4];
    {
        int r = (w << 4) + (lane >> 2);
        int c0 = (lane & 3) << 1;
#pragma unroll
        for (int ks = 0; ks < 4; ++ks) {
            Af[ks][0] = *(const unsigned*)(qh + (size_t)r * 64 + ks * 16 + c0);
            Af[ks][1] = *(const unsigned*)(qh + (size_t)(r + 8) * 64 + ks * 16 + c0);
            Af[ks][2] = *(const unsigned*)(qh + (size_t)r * 64 + ks * 16 + c0 + 8);
            Af[ks][3] = *(const unsigned*)(qh + (size_t)(r + 8) * 64 + ks * 16 + c0 + 8);
        }
    }

    // ---- scan state: 2 threads per query row, disjoint key parity ----
    const int q_own = tid >> 1;
    const int par = tid & 1;
    float tv[8]; int ti[8];
#pragma unroll
    for (int i = 0; i < 8; ++i) { tv[i] = -INFINITY; ti[i] = 0; }

    // K staging: thread -> key tid>>2, chunks {2*(tid&3), +1} (16B each)
    const int mykey = tid >> 2;
    const int cb2 = (tid & 3) << 1;
    uint4 pf0 = *(const uint4*)((const char*)kh + (size_t)mykey * 128 + cb2 * 16);
    uint4 pf1 = *(const uint4*)((const char*)kh + (size_t)mykey * 128 + (cb2 + 1) * 16);

    const int m = lane >> 3, ii = lane & 7;
    const int qr = (w << 4) + (lane >> 2);

    for (int kt = 0; kt < 32; ++kt) {
        __syncthreads();   // prev ldmatrix readers + prev scan readers done
        *(uint4*)(shK + mykey * 128 + ((cb2 ^ (mykey & 7)) << 4)) = pf0;
        *(uint4*)(shK + mykey * 128 + (((cb2 + 1) ^ (mykey & 7)) << 4)) = pf1;
        __syncthreads();
        if (kt < 31) {
            const char* src = (const char*)kh + ((size_t)(kt + 1) * 64 + mykey) * 128;
            pf0 = *(const uint4*)(src + cb2 * 16);
            pf1 = *(const uint4*)(src + (cb2 + 1) * 16);
        }

        // mma over 64 keys x 64 d, then store scores with explicit coords
#pragma unroll
        for (int np = 0; np < 4; ++np) {
            float c[8];
#pragma unroll
            for (int q = 0; q < 8; ++q) c[q] = 0.f;
#pragma unroll
            for (int ks = 0; ks < 4; ++ks) {
                int keyy = (np << 4) + ((m >> 1) << 3) + ii;
                int ch = (ks << 1) + (m & 1);
                unsigned br[4];
                unsigned sa = (unsigned)__cvta_generic_to_shared(
                    shK + keyy * 128 + ((ch ^ (keyy & 7)) << 4));
                ldsm4(br, sa);
                mma_bf16(c, Af[ks], br);
                mma_bf16(c + 4, Af[ks], br + 2);
            }
            // C frag: c0,c1 = (row, 2(lane&3)+{0,1}); c2,c3 = row+8; c4..7 = keys+8
            int kc = (np << 4) + ((lane & 3) << 1);
            shS[(kc    ) * 132 + qr    ] = c[0];
            shS[(kc + 1) * 132 + qr    ] = c[1];
            shS[(kc    ) * 132 + qr + 8] = c[2];
            shS[(kc + 1) * 132 + qr + 8] = c[3];
            shS[(kc + 8) * 132 + qr    ] = c[4];
            shS[(kc + 9) * 132 + qr    ] = c[5];
            shS[(kc + 8) * 132 + qr + 8] = c[6];
            shS[(kc + 9) * 132 + qr + 8] = c[7];
        }
        __syncthreads();   // scores visible

        // scalar scan of this thread's 32 keys (parity split)
        const int kb = kt << 6;
#pragma unroll 8
        for (int j = 0; j < 32; ++j) {
            int k = (j << 1) + par;
            float v = shS[k * 132 + q_own];
            if (v > tv[7]) ins8(tv, ti, v, kb + k);
        }
    }
    __syncthreads();   // all scans done; overlay shS region

    float* mv = shS;                 // [128][16] floats
    int*   mi = (int*)(shS + 2048);  // [128][16] ints (4096 floats total < 8448)

    // ---- exact sequential-fp32 rescore of own 8 candidates ----
    const float* kbase = g_k + (size_t)bh * S_ * HD_;
    {
        const float* qrow = g_q + ((size_t)bh * S_ + qblk + q_own) * HD_;
#pragma unroll
        for (int i = 0; i < 8; ++i) {
            mv[q_own * 16 + par * 8 + i] = dot64_seq(qrow, kbase + (size_t)ti[i] * HD_);
            mi[q_own * 16 + par * 8 + i] = ti[i];
        }
    }
    __syncthreads();

    // ---- per-row merge of 16, exact top-5, mask, softmax, scatter ----
    if (tid < 128) {
        const int q = tid;
        const int grow = qblk + q;
        float v16[16]; int k16[16];
#pragma unroll
        for (int i = 0; i < 16; ++i) { v16[i] = mv[q * 16 + i]; k16[i] = mi[q * 16 + i]; }
        // bring top-5 (desc) to front
#pragma unroll
        for (int s = 0; s < 5; ++s)
#pragma unroll
            for (int i = 15; i > s; --i)
                if (v16[i] > v16[i - 1]) {
                    float a = v16[i]; v16[i] = v16[i - 1]; v16[i - 1] = a;
                    int   b = k16[i]; k16[i] = k16[i - 1]; k16[i - 1] = b;
                }

        const float* qrow = g_q + ((size_t)bh * S_ + grow) * HD_;
        // sparse local-window mask (only |r-c|<=3 covered pairs can fail);
        // window dots use the same sequential chain as the candidate scores
        bool kp[5];
#pragma unroll
        for (int i = 0; i < 5; ++i) {
            int c = k16[i];
            int mn = min(grow, c), mx = max(grow, c);
            int ow = mn & ~1; if (ow > 2044) ow = 2044;
            bool keep = true;
            if (mx <= ow + 3) {
                float st0 = dot64_seq(qrow, kbase + (size_t)(ow + 0) * HD_);
                float st1 = dot64_seq(qrow, kbase + (size_t)(ow + 1) * HD_);
                float st2 = dot64_seq(qrow, kbase + (size_t)(ow + 2) * HD_);
                float st3 = dot64_seq(qrow, kbase + (size_t)(ow + 3) * HD_);
                float mn01 = fminf(st0, st1), mx01 = fmaxf(st0, st1);
                float mn23 = fminf(st2, st3), mx23 = fmaxf(st2, st3);
                float thr = fminf(fmaxf(mn01, mn23), fminf(mx01, mx23));
                int ci = c - ow;
                float cv = (ci == 0) ? st0 : (ci == 1) ? st1 : (ci == 2) ? st2 : st3;
                keep = (cv >= thr);
            }
            kp[i] = keep;
        }

        float sm = -INFINITY;
#pragma unroll
        for (int i = 0; i < 5; ++i) if (kp[i]) sm = fmaxf(sm, v16[i]);
        sm *= 0.125f;
        float p[5]; float sum = 0.f;
#pragma unroll
        for (int i = 0; i < 5; ++i) {
            p[i] = kp[i] ? expf(v16[i] * 0.125f - sm) : 0.f;
            sum += p[i];
        }
        float inv = 1.f / sum;
#pragma unroll
        for (int i = 0; i < 5; ++i) {
            if (kp[i]) {
                float pi = p[i] * inv;
                int c = k16[i];
                if (out_attn) out_attn[((size_t)bh * S_ + grow) * S_ + c] = pi;
                spw[q][i] = pi * g_fi[(size_t)bh * S_ + c];
                spidx[q][i] = (unsigned short)c;
            } else {
                spw[q][i] = 0.f;
                spidx[q][i] = 0;
            }
        }
    }
    __syncthreads();

    // ---- sparse ctx: 2 threads/row, 32 dims each ----
    {
        const int row = tid >> 1;
        const int h0 = (tid & 1) << 5;
        float4 a[8];
#pragma unroll
        for (int j = 0; j < 8; ++j) a[j] = make_float4(0.f, 0.f, 0.f, 0.f);
        const float* vb = g_v + (size_t)bh * S_ * HD_;
#pragma unroll
        for (int i = 0; i < 5; ++i) {
            float wv = spw[row][i];
            int c = spidx[row][i];
            const float4* vr = (const float4*)(vb + (size_t)c * 64 + h0);
#pragma unroll
            for (int j = 0; j < 8; ++j) {
                float4 vv = vr[j];
                a[j].x += wv * vv.x; a[j].y += wv * vv.y;
                a[j].z += wv * vv.z; a[j].w += wv * vv.w;
            }
        }
        int b = bh >> 3, hh = bh & 7;
        float* dp = g_ctx + ((size_t)(b * S_) + qblk + row) * D_ + (hh << 6) + h0;
#pragma unroll
        for (int j = 0; j < 8; ++j) ((float4*)dp)[j] = a[j];
    }
}

// ---------------------------------------------------------------------------
extern "C" void kernel_launch(void* const* d_in, const int* in_sizes, int n_in,
                              void* d_out, int out_size)
{
    const float* x      = (const float*)d_in[0];
    const float* w_qkv  = (const float*)d_in[1];
    const float* b_qkv  = (const float*)d_in[2];
    const float* w_proj = (const float*)d_in[3];
    const float* b_proj = (const float*)d_in[4];
    float* out = (float*)d_out;

    const size_t nproj = (size_t)B_ * S_ * D_;
    const size_t nattn = (size_t)NBH * S_ * S_;
    float* out_attn = ((size_t)out_size >= nproj + nattn) ? (out + nproj) : nullptr;

    // 1) fused QKV projection -> head-layout q/k/v (+ bf16 q,k planes)
    sgemm_pipe<<<dim3(24, 32), 256>>>(x, w_qkv, b_qkv, nullptr, B_ * S_, 3 * D_, D_, 1);
    // 2) feature importance per (b,h,s)
    fi_kernel<<<128, 256>>>();
    // 3) tensor-core scores / exact top-5 / mask / softmax / sparse ctx
    //    (zero-fills its own attn rows)
    attn_mma2<<<dim3(S_ / 128, NBH), 256>>>(out_attn);
    // 4) output projection
    sgemm_pipe<<<dim3(8, 32), 256>>>(nullptr, w_proj, b_proj, out, B_ * S_, D_, D_, 2);
}

// round 8
// speedup vs baseline: 1.9108x; 1.1786x over previous
#include <cuda_runtime.h>
#include <cuda_bf16.h>
#include <math.h>

#define B_  2
#define S_  2048
#define D_  512
#define H_  8
#define HD_ 64
#define NBH 16   // B_*H_

// Scratch (static __device__ — no allocations allowed)
__device__ float g_q[(size_t)NBH * S_ * HD_];
__device__ float g_k[(size_t)NBH * S_ * HD_];
__device__ float g_v[(size_t)NBH * S_ * HD_];
__device__ __nv_bfloat16 g_qh[(size_t)NBH * S_ * HD_];
__device__ __nv_bfloat16 g_kh[(size_t)NBH * S_ * HD_];
__device__ float g_fi[(size_t)NBH * S_];
__device__ float g_ctx[(size_t)B_ * S_ * D_];

// ---------------------------------------------------------------------------
// Pipelined fp32 GEMM (FROZEN numerics: k-ascending single-acc FFMA chain).
// mode 1: QKV epilogue -> scatter to g_q/g_k/g_v (+ bf16 q,k planes)
// ---------------------------------------------------------------------------
__global__ __launch_bounds__(256)
void sgemm_pipe(const float* __restrict__ A, const float* __restrict__ Bm,
                const float* __restrict__ bias, float* __restrict__ C,
                int M, int N, int K, int mode)
{
    __shared__ float As[16][132];   // transposed: As[k][m], padded
    __shared__ float Bs[16][64];

    const int tid = threadIdx.x;
    const int tx = tid & 15, ty = tid >> 4;
    const int m0 = blockIdx.y << 7, n0 = blockIdx.x << 6;

    const int arow = tid >> 1;            // 0..127
    const int ac   = (tid & 1) << 3;      // k base 0 or 8
    const int brow = tid >> 4;            // 0..15
    const int bc   = (tid & 15) << 2;     // 0..60

    const float* Ap = A  + (size_t)(m0 + arow) * K + ac;
    const float* Bp = Bm + (size_t)brow * N + n0 + bc;

    float acc[8][4];
#pragma unroll
    for (int i = 0; i < 8; ++i)
#pragma unroll
        for (int j = 0; j < 4; ++j) acc[i][j] = 0.f;

    float4 pa0 = *(const float4*)(Ap);
    float4 pa1 = *(const float4*)(Ap + 4);
    float4 pb  = *(const float4*)(Bp);

    const int ty8 = ty << 3, tx4 = tx << 2;

    for (int k0 = 0; k0 < K; k0 += 16) {
        __syncthreads();
        As[ac + 0][arow] = pa0.x;
        As[ac + 1][arow] = pa0.y;
        As[ac + 2][arow] = pa0.z;
        As[ac + 3][arow] = pa0.w;
        As[ac + 4][arow] = pa1.x;
        As[ac + 5][arow] = pa1.y;
        As[ac + 6][arow] = pa1.z;
        As[ac + 7][arow] = pa1.w;
        *(float4*)&Bs[brow][bc] = pb;
        __syncthreads();
        if (k0 + 16 < K) {
            pa0 = *(const float4*)(Ap + k0 + 16);
            pa1 = *(const float4*)(Ap + k0 + 20);
            pb  = *(const float4*)(Bp + (size_t)(k0 + 16) * N);
        }
#pragma unroll
        for (int kk = 0; kk < 16; ++kk) {
            float4 a0 = *(const float4*)&As[kk][ty8];
            float4 a1 = *(const float4*)&As[kk][ty8 + 4];
            float4 bv = *(const float4*)&Bs[kk][tx4];
            float am[8] = {a0.x,a0.y,a0.z,a0.w,a1.x,a1.y,a1.z,a1.w};
            float bn[4] = {bv.x,bv.y,bv.z,bv.w};
#pragma unroll
            for (int i = 0; i < 8; ++i)
#pragma unroll
                for (int j = 0; j < 4; ++j)
                    acc[i][j] += am[i] * bn[j];
        }
    }

    const int n_base = n0 + tx4;
    if (mode != 1) {
        const float* bp2 = bias + n_base;
        float4 bb = make_float4(bp2[0], bp2[1], bp2[2], bp2[3]);
#pragma unroll
        for (int i = 0; i < 8; ++i) {
            int m = m0 + ty8 + i;
            float4 v = make_float4(acc[i][0] + bb.x, acc[i][1] + bb.y,
                                   acc[i][2] + bb.z, acc[i][3] + bb.w);
            *(float4*)(C + (size_t)m * N + n_base) = v;
        }
    } else {
        int t3 = n_base >> 9;            // 0:q 1:k 2:v
        int cc = n_base & 511;
        int h = cc >> 6, hd = cc & 63;
        float* dst = (t3 == 0) ? g_q : (t3 == 1) ? g_k : g_v;
        __nv_bfloat16* dsth = (t3 == 0) ? g_qh : (t3 == 1) ? g_kh : nullptr;
        const float* bp2 = bias + n_base;
        float4 bb = make_float4(bp2[0], bp2[1], bp2[2], bp2[3]);
#pragma unroll
        for (int i = 0; i < 8; ++i) {
            int m = m0 + ty8 + i;
            int b = m >> 11, s = m & 2047;
            size_t off = (((size_t)(b * H_ + h) * S_) + s) * HD_ + hd;
            float v0 = acc[i][0] + bb.x, v1 = acc[i][1] + bb.y;
            float v2 = acc[i][2] + bb.z, v3 = acc[i][3] + bb.w;
            *(float4*)(dst + off) = make_float4(v0, v1, v2, v3);
            if (dsth) {
                unsigned p0 = (unsigned)__bfloat16_as_ushort(__float2bfloat16_rn(v0)) |
                              ((unsigned)__bfloat16_as_ushort(__float2bfloat16_rn(v1)) << 16);
                unsigned p1 = (unsigned)__bfloat16_as_ushort(__float2bfloat16_rn(v2)) |
                              ((unsigned)__bfloat16_as_ushort(__float2bfloat16_rn(v3)) << 16);
                *(uint2*)(dsth + off) = make_uint2(p0, p1);
            }
        }
    }
}

// ---------------------------------------------------------------------------
__global__ void fi_kernel()
{
    int i = blockIdx.x * blockDim.x + threadIdx.x;
    if (i >= NBH * S_) return;
    const float4* q = (const float4*)(g_q + (size_t)i * HD_);
    float s = 0.f;
#pragma unroll
    for (int u = 0; u < 16; ++u) {
        float4 v = q[u];
        s += v.x + v.y + v.z + v.w;
    }
    float mval = s * (1.f / 64.f);
    g_fi[i] = 1.f / (1.f + expf(-mval));
}

// ---------------------------------------------------------------------------
__device__ __forceinline__ void ldsm4(unsigned* r, unsigned saddr)
{
    asm volatile("ldmatrix.sync.aligned.m8n8.x4.shared.b16 {%0,%1,%2,%3}, [%4];"
                 : "=r"(r[0]), "=r"(r[1]), "=r"(r[2]), "=r"(r[3]) : "r"(saddr));
}

__device__ __forceinline__ void mma_bf16(float* c, const unsigned* a, const unsigned* b)
{
    asm volatile("mma.sync.aligned.m16n8k16.row.col.f32.bf16.bf16.f32 "
                 "{%0,%1,%2,%3},{%4,%5,%6,%7},{%8,%9},{%0,%1,%2,%3};"
                 : "+f"(c[0]), "+f"(c[1]), "+f"(c[2]), "+f"(c[3])
                 : "r"(a[0]), "r"(a[1]), "r"(a[2]), "r"(a[3]),
                   "r"(b[0]), "r"(b[1]));
}

// Sequential d-ascending single-accumulator FFMA chain (LOAD-BEARING: exact
// tie resolution matching the reference — do not change).
__device__ __forceinline__ float dot64_seq(const float* __restrict__ a,
                                           const float* __restrict__ b)
{
    const float4* A4 = (const float4*)a;
    const float4* B4 = (const float4*)b;
    float s = 0.f;
#pragma unroll
    for (int i = 0; i < 16; ++i) {
        float4 x = A4[i], y = B4[i];
        s = __fmaf_rn(x.x, y.x, s);
        s = __fmaf_rn(x.y, y.y, s);
        s = __fmaf_rn(x.z, y.z, s);
        s = __fmaf_rn(x.w, y.w, s);
    }
    return s;
}

// sorted-desc top-5 insert (pre-checked by caller: v > tv[4])
__device__ __forceinline__ void ins5(float* tv, int* ti, float v, int idx)
{
    tv[4] = v; ti[4] = idx;
#pragma unroll
    for (int u = 4; u > 0; --u) {
        if (tv[u] > tv[u - 1]) {
            float a = tv[u]; tv[u] = tv[u - 1]; tv[u - 1] = a;
            int   b = ti[u]; ti[u] = ti[u - 1]; ti[u - 1] = b;
        }
    }
}

// ---------------------------------------------------------------------------
// Tensor-core approx scores with IN-REGISTER per-lane top-5 per row (no smem
// score roundtrip) -> 20 candidates/row -> EXACT dot64_seq rescore -> top-5 ->
// window mask -> softmax -> attn scatter + sparse ctx.
// Block: 128 queries of one (b,h); 256 threads = 8 warps; 128-key tiles.
// ---------------------------------------------------------------------------
__global__ __launch_bounds__(256)
void attn_mma3(float* __restrict__ out_attn)
{
    __shared__ __align__(16) unsigned char shK[16384];  // 128 keys x 128B swizzled
    __shared__ float mbv[128 * 20];                     // [row][lane4][5]
    __shared__ int   mbi[128 * 20];
    __shared__ float spw[128][5];
    __shared__ unsigned short spidx[128][5];

    const int tid = threadIdx.x;
    const int w = tid >> 5, lane = tid & 31;
    const int bh = blockIdx.y;
    const int qblk = blockIdx.x << 7;

    // in-kernel zero-fill of this block's attn rows (overlaps the mma loop)
    if (out_attn) {
        float4 z4 = make_float4(0.f, 0.f, 0.f, 0.f);
        float4* zp = (float4*)(out_attn + ((size_t)bh * S_ + qblk) * S_);
        for (int i = tid; i < 128 * S_ / 4; i += 256) zp[i] = z4;
    }

    const __nv_bfloat16* qh = g_qh + ((size_t)bh * S_ + qblk) * HD_;
    const __nv_bfloat16* kh = g_kh + (size_t)bh * S_ * HD_;

    // ---- A fragments for this warp's 16 rows (R7-verified layout) ----
    unsigned Af[4][4];
    {
        int r = (w << 4) + (lane >> 2);
        int c0 = (lane & 3) << 1;
#pragma unroll
        for (int ks = 0; ks < 4; ++ks) {
            Af[ks][0] = *(const unsigned*)(qh + (size_t)r * 64 + ks * 16 + c0);
            Af[ks][1] = *(const unsigned*)(qh + (size_t)(r + 8) * 64 + ks * 16 + c0);
            Af[ks][2] = *(const unsigned*)(qh + (size_t)r * 64 + ks * 16 + c0 + 8);
            Af[ks][3] = *(const unsigned*)(qh + (size_t)(r + 8) * 64 + ks * 16 + c0 + 8);
        }
    }

    // per-thread top-5 for rowA (w*16 + lane/4) and rowB (+8)
    float tvA[5], tvB[5]; int tiA[5], tiB[5];
#pragma unroll
    for (int i = 0; i < 5; ++i) {
        tvA[i] = -INFINITY; tvB[i] = -INFINITY; tiA[i] = 0; tiB[i] = 0;
    }

    // K staging: 2 threads per key, 4 x 16B chunks each (R2 pattern)
    const int mykey = tid >> 1;
    const int cbase = (tid & 1) << 2;
    uint4 pf[4];
#pragma unroll
    for (int j = 0; j < 4; ++j)
        pf[j] = *(const uint4*)((const char*)kh + (size_t)mykey * 128 + (cbase + j) * 16);

    const int m = lane >> 3, ii = lane & 7;

    for (int kt = 0; kt < 16; ++kt) {
        __syncthreads();
#pragma unroll
        for (int j = 0; j < 4; ++j)
            *(uint4*)(shK + mykey * 128 + (((cbase + j) ^ (mykey & 7)) << 4)) = pf[j];
        __syncthreads();
        if (kt < 15) {
            const char* src = (const char*)kh + ((size_t)(kt + 1) * 128 + mykey) * 128;
#pragma unroll
            for (int j = 0; j < 4; ++j)
                pf[j] = *(const uint4*)(src + (cbase + j) * 16);
        }

#pragma unroll
        for (int np = 0; np < 8; ++np) {
            float c[8];
#pragma unroll
            for (int q = 0; q < 8; ++q) c[q] = 0.f;
#pragma unroll
            for (int ks = 0; ks < 4; ++ks) {
                int keyy = (np << 4) + ((m >> 1) << 3) + ii;
                int ch = (ks << 1) + (m & 1);
                unsigned br[4];
                unsigned sa = (unsigned)__cvta_generic_to_shared(
                    shK + keyy * 128 + ((ch ^ (keyy & 7)) << 4));
                ldsm4(br, sa);
                mma_bf16(c, Af[ks], br);
                mma_bf16(c + 4, Af[ks], br + 2);
            }
            // C frag coords (R7-verified): rowA=(w16+lane/4), rowB=+8,
            // keys kb..kb+1 (c0..c3), kb+8..kb+9 (c4..c7)
            int kb = (kt << 7) + (np << 4) + ((lane & 3) << 1);
            if (c[0] > tvA[4]) ins5(tvA, tiA, c[0], kb);
            if (c[1] > tvA[4]) ins5(tvA, tiA, c[1], kb + 1);
            if (c[2] > tvB[4]) ins5(tvB, tiB, c[2], kb);
            if (c[3] > tvB[4]) ins5(tvB, tiB, c[3], kb + 1);
            if (c[4] > tvA[4]) ins5(tvA, tiA, c[4], kb + 8);
            if (c[5] > tvA[4]) ins5(tvA, tiA, c[5], kb + 9);
            if (c[6] > tvB[4]) ins5(tvB, tiB, c[6], kb + 8);
            if (c[7] > tvB[4]) ins5(tvB, tiB, c[7], kb + 9);
        }
    }

    // ---- dump 5 candidates per (row, lane-group) to smem ----
    {
        int rowA = (w << 4) + (lane >> 2);
        int rowB = rowA + 8;
        int l = lane & 3;
#pragma unroll
        for (int u = 0; u < 5; ++u) {
            mbv[rowA * 20 + l * 5 + u] = tvA[u];
            mbi[rowA * 20 + l * 5 + u] = tiA[u];
            mbv[rowB * 20 + l * 5 + u] = tvB[u];
            mbi[rowB * 20 + l * 5 + u] = tiB[u];
        }
    }
    __syncthreads();

    // ---- exact sequential-fp32 rescore: 2 threads/row, 10 candidates each ----
    const float* kbase = g_k + (size_t)bh * S_ * HD_;
    {
        const int q_own = tid >> 1, par = tid & 1;
        const float* qrow = g_q + ((size_t)bh * S_ + qblk + q_own) * HD_;
#pragma unroll
        for (int i = 0; i < 10; ++i) {
            int slot = q_own * 20 + (par * 2 + (i >= 5 ? 1 : 0)) * 5 + (i % 5);
            mbv[slot] = dot64_seq(qrow, kbase + (size_t)mbi[slot] * HD_);
        }
    }
    __syncthreads();

    // ---- per-row merge of 20, exact top-5, mask, softmax, scatter ----
    if (tid < 128) {
        const int q = tid;
        const int grow = qblk + q;
        float v20[20]; int k20[20];
#pragma unroll
        for (int i = 0; i < 20; ++i) { v20[i] = mbv[q * 20 + i]; k20[i] = mbi[q * 20 + i]; }
        // bring top-5 (desc) to front
#pragma unroll
        for (int s = 0; s < 5; ++s)
#pragma unroll
            for (int i = 19; i > s; --i)
                if (v20[i] > v20[i - 1]) {
                    float a = v20[i]; v20[i] = v20[i - 1]; v20[i - 1] = a;
                    int   b = k20[i]; k20[i] = k20[i - 1]; k20[i - 1] = b;
                }

        const float* qrow = g_q + ((size_t)bh * S_ + grow) * HD_;
        bool kp[5];
#pragma unroll
        for (int i = 0; i < 5; ++i) {
            int c = k20[i];
            int mn = min(grow, c), mx = max(grow, c);
            int ow = mn & ~1; if (ow > 2044) ow = 2044;
            bool keep = true;
            if (mx <= ow + 3) {
                float st0 = dot64_seq(qrow, kbase + (size_t)(ow + 0) * HD_);
                float st1 = dot64_seq(qrow, kbase + (size_t)(ow + 1) * HD_);
                float st2 = dot64_seq(qrow, kbase + (size_t)(ow + 2) * HD_);
                float st3 = dot64_seq(qrow, kbase + (size_t)(ow + 3) * HD_);
                float mn01 = fminf(st0, st1), mx01 = fmaxf(st0, st1);
                float mn23 = fminf(st2, st3), mx23 = fmaxf(st2, st3);
                float thr = fminf(fmaxf(mn01, mn23), fminf(mx01, mx23));
                int ci = c - ow;
                float cv = (ci == 0) ? st0 : (ci == 1) ? st1 : (ci == 2) ? st2 : st3;
                keep = (cv >= thr);
            }
            kp[i] = keep;
        }

        float sm = -INFINITY;
#pragma unroll
        for (int i = 0; i < 5; ++i) if (kp[i]) sm = fmaxf(sm, v20[i]);
        sm *= 0.125f;
        float p[5]; float sum = 0.f;
#pragma unroll
        for (int i = 0; i < 5; ++i) {
            p[i] = kp[i] ? expf(v20[i] * 0.125f - sm) : 0.f;
            sum += p[i];
        }
        float inv = 1.f / sum;
#pragma unroll
        for (int i = 0; i < 5; ++i) {
            if (kp[i]) {
                float pi = p[i] * inv;
                int c = k20[i];
                if (out_attn) out_attn[((size_t)bh * S_ + grow) * S_ + c] = pi;
                spw[q][i] = pi * g_fi[(size_t)bh * S_ + c];
                spidx[q][i] = (unsigned short)c;
            } else {
                spw[q][i] = 0.f;
                spidx[q][i] = 0;
            }
        }
    }
    __syncthreads();

    // ---- sparse ctx: 2 threads/row, 32 dims each ----
    {
        const int row = tid >> 1;
        const int h0 = (tid & 1) << 5;
        float4 a[8];
#pragma unroll
        for (int j = 0; j < 8; ++j) a[j] = make_float4(0.f, 0.f, 0.f, 0.f);
        const float* vb = g_v + (size_t)bh * S_ * HD_;
#pragma unroll
        for (int i = 0; i < 5; ++i) {
            float wv = spw[row][i];
            int c = spidx[row][i];
            const float4* vr = (const float4*)(vb + (size_t)c * 64 + h0);
#pragma unroll
            for (int j = 0; j < 8; ++j) {
                float4 vv = vr[j];
                a[j].x += wv * vv.x; a[j].y += wv * vv.y;
                a[j].z += wv * vv.z; a[j].w += wv * vv.w;
            }
        }
        int b = bh >> 3, hh = bh & 7;
        float* dp = g_ctx + ((size_t)(b * S_) + qblk + row) * D_ + (hh << 6) + h0;
#pragma unroll
        for (int j = 0; j < 8; ++j) ((float4*)dp)[j] = a[j];
    }
}

// ---------------------------------------------------------------------------
// 3xTF32 tensor-core output projection: out = g_ctx @ w_proj + bias.
// Block tile 128(M) x 64(N), 8 warps in 4x2 grid (32x32 each), K chunks of 32.
// ---------------------------------------------------------------------------
__device__ __forceinline__ void tf32split(float x, unsigned& hi, unsigned& lo)
{
    unsigned h;
    asm("cvt.rna.tf32.f32 %0, %1;" : "=r"(h) : "f"(x));
    float lf = x - __uint_as_float(h);
    unsigned l;
    asm("cvt.rna.tf32.f32 %0, %1;" : "=r"(l) : "f"(lf));
    hi = h; lo = l;
}

__device__ __forceinline__ void mma_tf32(float* c, const unsigned* a, const unsigned* b)
{
    asm volatile("mma.sync.aligned.m16n8k8.row.col.f32.tf32.tf32.f32 "
                 "{%0,%1,%2,%3},{%4,%5,%6,%7},{%8,%9},{%0,%1,%2,%3};"
                 : "+f"(c[0]), "+f"(c[1]), "+f"(c[2]), "+f"(c[3])
                 : "r"(a[0]), "r"(a[1]), "r"(a[2]), "r"(a[3]),
                   "r"(b[0]), "r"(b[1]));
}

__global__ __launch_bounds__(256)
void proj_tf32(const float* __restrict__ Bm, const float* __restrict__ bias,
               float* __restrict__ C)
{
    __shared__ float As[128 * 36];   // [m][k] pad 36 -> frag LDS conflict-free
    __shared__ float Bs[32 * 72];    // [k][n] pad 72 -> frag LDS conflict-free

    const int tid = threadIdx.x;
    const int lane = tid & 31, w = tid >> 5;
    const int wm = w >> 1, wn = w & 1;          // 4x2 warp grid (32x32 tiles)
    const int m0 = blockIdx.y << 7, n0 = blockIdx.x << 6;
    const int gr = lane >> 2, gc = lane & 3;

    float acc[2][4][4];
#pragma unroll
    for (int a = 0; a < 2; ++a)
#pragma unroll
        for (int b = 0; b < 4; ++b)
#pragma unroll
            for (int cj = 0; cj < 4; ++cj) acc[a][b][cj] = 0.f;

    const int arow = tid >> 1, ak = (tid & 1) << 4;   // A: 16 floats/thread
    const int brow = tid >> 3, bn = (tid & 7) << 3;   // B: 8 floats/thread

    for (int kc = 0; kc < 512; kc += 32) {
        __syncthreads();
        {
            const float* Ap = g_ctx + (size_t)(m0 + arow) * 512 + kc + ak;
            float4 a0 = *(const float4*)(Ap);
            float4 a1 = *(const float4*)(Ap + 4);
            float4 a2 = *(const float4*)(Ap + 8);
            float4 a3 = *(const float4*)(Ap + 12);
            *(float4*)&As[arow * 36 + ak + 0]  = a0;
            *(float4*)&As[arow * 36 + ak + 4]  = a1;
            *(float4*)&As[arow * 36 + ak + 8]  = a2;
            *(float4*)&As[arow * 36 + ak + 12] = a3;
            const float* Bp = Bm + (size_t)(kc + brow) * 512 + n0 + bn;
            *(float4*)&Bs[brow * 72 + bn + 0] = *(const float4*)(Bp);
            *(float4*)&Bs[brow * 72 + bn + 4] = *(const float4*)(Bp + 4);
        }
        __syncthreads();

#pragma unroll
        for (int kk = 0; kk < 4; ++kk) {
            unsigned ah[2][4], al[2][4];
#pragma unroll
            for (int mt = 0; mt < 2; ++mt) {
                int mrow = (wm << 5) + (mt << 4);
                float a_0 = As[(mrow + gr) * 36 + (kk << 3) + gc];
                float a_1 = As[(mrow + gr + 8) * 36 + (kk << 3) + gc];
                float a_2 = As[(mrow + gr) * 36 + (kk << 3) + gc + 4];
                float a_3 = As[(mrow + gr + 8) * 36 + (kk << 3) + gc + 4];
                tf32split(a_0, ah[mt][0], al[mt][0]);
                tf32split(a_1, ah[mt][1], al[mt][1]);
                tf32split(a_2, ah[mt][2], al[mt][2]);
                tf32split(a_3, ah[mt][3], al[mt][3]);
            }
            unsigned bhv[4][2], blv[4][2];
#pragma unroll
            for (int nt = 0; nt < 4; ++nt) {
                int ncol = (wn << 5) + (nt << 3) + gr;
                float b_0 = Bs[((kk << 3) + gc) * 72 + ncol];
                float b_1 = Bs[((kk << 3) + gc + 4) * 72 + ncol];
                tf32split(b_0, bhv[nt][0], blv[nt][0]);
                tf32split(b_1, bhv[nt][1], blv[nt][1]);
            }
#pragma unroll
            for (int mt = 0; mt < 2; ++mt)
#pragma unroll
                for (int nt = 0; nt < 4; ++nt) {
                    mma_tf32(acc[mt][nt], al[mt], bhv[nt]);   // lo*hi
                    mma_tf32(acc[mt][nt], ah[mt], blv[nt]);   // hi*lo
                    mma_tf32(acc[mt][nt], ah[mt], bhv[nt]);   // hi*hi
                }
        }
    }

    // epilogue: C frag (m16n8 f32): c0,c1 = (gr, 2gc..2gc+1); c2,c3 = (gr+8, ..)
#pragma unroll
    for (int mt = 0; mt < 2; ++mt)
#pragma unroll
        for (int nt = 0; nt < 4; ++nt) {
            int row = m0 + (wm << 5) + (mt << 4) + gr;
            int col = n0 + (wn << 5) + (nt << 3) + (gc << 1);
            float b0v = bias[col], b1v = bias[col + 1];
            *(float2*)(C + (size_t)row * 512 + col) =
                make_float2(acc[mt][nt][0] + b0v, acc[mt][nt][1] + b1v);
            *(float2*)(C + (size_t)(row + 8) * 512 + col) =
                make_float2(acc[mt][nt][2] + b0v, acc[mt][nt][3] + b1v);
        }
}

// ---------------------------------------------------------------------------
extern "C" void kernel_launch(void* const* d_in, const int* in_sizes, int n_in,
                              void* d_out, int out_size)
{
    const float* x      = (const float*)d_in[0];
    const float* w_qkv  = (const float*)d_in[1];
    const float* b_qkv  = (const float*)d_in[2];
    const float* w_proj = (const float*)d_in[3];
    const float* b_proj = (const float*)d_in[4];
    float* out = (float*)d_out;

    const size_t nproj = (size_t)B_ * S_ * D_;
    const size_t nattn = (size_t)NBH * S_ * S_;
    float* out_attn = ((size_t)out_size >= nproj + nattn) ? (out + nproj) : nullptr;

    // 1) fused QKV projection -> head-layout q/k/v (+ bf16 q,k planes) [FROZEN]
    sgemm_pipe<<<dim3(24, 32), 256>>>(x, w_qkv, b_qkv, nullptr, B_ * S_, 3 * D_, D_, 1);
    // 2) feature importance per (b,h,s)
    fi_kernel<<<128, 256>>>();
    // 3) tensor-core scores / exact top-5 / mask / softmax / sparse ctx
    attn_mma3<<<dim3(S_ / 128, NBH), 256>>>(out_attn);
    // 4) output projection (3xTF32 tensor cores)
    proj_tf32<<<dim3(8, 32), 256>>>(w_proj, b_proj, out);
}